// round 2
// baseline (speedup 1.0000x reference)
#include <cuda_runtime.h>

#define B_   8
#define T_   16
#define H_   64
#define W_   64
#define CIN  32
#define F_   64
#define NC   256          // 4*F (gates i,f,c,o stacked)
#define XS_PITCH 101      // padded pitch for halo tiles (conflict-avoidance)

// Persistent recurrent state (no allocation allowed). FIRST-step template
// ignores these on read, so no zero-init is needed -> deterministic replays.
__device__ float g_h[2][B_ * H_ * W_ * F_];
__device__ float g_c[B_ * H_ * W_ * F_];

__device__ __forceinline__ float hsig(float x) {
    // jax.nn.hard_sigmoid = relu6(x+3)/6 = clip((x+3)/6, 0, 1)
    return __saturatef((x + 3.0f) * 0.16666667f);
}

// One ConvLSTM timestep. Block = (batch, 8x8 spatial tile), 256 threads.
// C tile: 64 spatial rows x 256 out-cols. Thread tile: 4 x 16.
template<bool FIRST>
__global__ __launch_bounds__(256, 2)
void step_kernel(const float* __restrict__ x,
                 const float* __restrict__ Wt,   // (3,3,32,256)
                 const float* __restrict__ Ut,   // (3,3,64,256)
                 const float* __restrict__ bias, // (256)
                 int t, int hsel,
                 float* __restrict__ outbuf, int last)
{
    extern __shared__ float smem[];
    float* ws = smem;                         // weight slice: up to 64*256
    float* xs = smem + F_ * NC;               // x halo: [32][101]
    float* hs = xs + CIN * XS_PITCH;          // h halo: [64][101]

    const int tid = threadIdx.x;
    const int b   = blockIdx.y;
    const int ty0 = (blockIdx.x >> 3) << 3;
    const int tx0 = (blockIdx.x & 7) << 3;

    const int mt  = tid >> 4;        // 0..15 -> (tile row, col-half)
    const int nt  = tid & 15;        // out-col group: cols g*64 + nt*4 + j
    const int sy  = mt >> 1;         // thread's tile row
    const int sxb = (mt & 1) << 2;   // thread's tile col base

    // ---- stage x halo tile: xs[c][p], p = py*10 + px ----
    {
        const float* xb = x + (size_t)(b * T_ + t) * H_ * W_ * CIN;
        for (int j = tid; j < 100 * (CIN / 4); j += 256) {
            int p  = j >> 3;
            int v  = j & 7;
            int py = p / 10, px = p - 10 * py;
            int gy = ty0 + py - 1, gx = tx0 + px - 1;
            float4 val = make_float4(0.f, 0.f, 0.f, 0.f);
            if ((unsigned)gy < H_ && (unsigned)gx < W_)
                val = *(const float4*)(xb + ((size_t)gy * W_ + gx) * CIN + v * 4);
            int c0 = v * 4;
            xs[(c0 + 0) * XS_PITCH + p] = val.x;
            xs[(c0 + 1) * XS_PITCH + p] = val.y;
            xs[(c0 + 2) * XS_PITCH + p] = val.z;
            xs[(c0 + 3) * XS_PITCH + p] = val.w;
        }
    }
    // ---- stage h halo tile ----
    if (!FIRST) {
        const float* hb = g_h[hsel] + (size_t)b * H_ * W_ * F_;
        for (int j = tid; j < 100 * (F_ / 4); j += 256) {
            int p  = j >> 4;
            int v  = j & 15;
            int py = p / 10, px = p - 10 * py;
            int gy = ty0 + py - 1, gx = tx0 + px - 1;
            float4 val = make_float4(0.f, 0.f, 0.f, 0.f);
            if ((unsigned)gy < H_ && (unsigned)gx < W_)
                val = *(const float4*)(hb + ((size_t)gy * W_ + gx) * F_ + v * 4);
            int c0 = v * 4;
            hs[(c0 + 0) * XS_PITCH + p] = val.x;
            hs[(c0 + 1) * XS_PITCH + p] = val.y;
            hs[(c0 + 2) * XS_PITCH + p] = val.z;
            hs[(c0 + 3) * XS_PITCH + p] = val.w;
        }
    }

    float acc[4][16];
    #pragma unroll
    for (int m = 0; m < 4; ++m)
        #pragma unroll
        for (int r = 0; r < 16; ++r) acc[m][r] = 0.f;

    // ================= input conv: z += conv(x_t, W) =================
    for (int k9 = 0; k9 < 9; ++k9) {
        __syncthreads();   // tiles staged (k9==0) / previous ws reads done
        {
            const float4* src = (const float4*)(Wt + (size_t)k9 * CIN * NC);
            float4* dst = (float4*)ws;
            #pragma unroll
            for (int j = 0; j < (CIN * NC / 4) / 256; ++j)
                dst[tid + j * 256] = src[tid + j * 256];
        }
        __syncthreads();
        const int ky = k9 / 3, kx = k9 - 3 * (k9 / 3);
        const float* ap = xs + (sy + ky) * 10 + sxb + kx;
        const float* wp = ws + nt * 4;
        #pragma unroll 4
        for (int c = 0; c < CIN; ++c) {
            float a0 = ap[0], a1 = ap[1], a2 = ap[2], a3 = ap[3];
            #pragma unroll
            for (int g = 0; g < 4; ++g) {
                float4 wv = *(const float4*)(wp + g * 64);
                acc[0][g*4+0] += a0 * wv.x; acc[0][g*4+1] += a0 * wv.y;
                acc[0][g*4+2] += a0 * wv.z; acc[0][g*4+3] += a0 * wv.w;
                acc[1][g*4+0] += a1 * wv.x; acc[1][g*4+1] += a1 * wv.y;
                acc[1][g*4+2] += a1 * wv.z; acc[1][g*4+3] += a1 * wv.w;
                acc[2][g*4+0] += a2 * wv.x; acc[2][g*4+1] += a2 * wv.y;
                acc[2][g*4+2] += a2 * wv.z; acc[2][g*4+3] += a2 * wv.w;
                acc[3][g*4+0] += a3 * wv.x; acc[3][g*4+1] += a3 * wv.y;
                acc[3][g*4+2] += a3 * wv.z; acc[3][g*4+3] += a3 * wv.w;
            }
            ap += XS_PITCH;
            wp += NC;
        }
    }

    // ================= recurrent conv: z += conv(h, U) =================
    if (!FIRST) {
        for (int k9 = 0; k9 < 9; ++k9) {
            __syncthreads();
            {
                const float4* src = (const float4*)(Ut + (size_t)k9 * F_ * NC);
                float4* dst = (float4*)ws;
                #pragma unroll
                for (int j = 0; j < (F_ * NC / 4) / 256; ++j)
                    dst[tid + j * 256] = src[tid + j * 256];
            }
            __syncthreads();
            const int ky = k9 / 3, kx = k9 - 3 * (k9 / 3);
            const float* ap = hs + (sy + ky) * 10 + sxb + kx;
            const float* wp = ws + nt * 4;
            #pragma unroll 4
            for (int c = 0; c < F_; ++c) {
                float a0 = ap[0], a1 = ap[1], a2 = ap[2], a3 = ap[3];
                #pragma unroll
                for (int g = 0; g < 4; ++g) {
                    float4 wv = *(const float4*)(wp + g * 64);
                    acc[0][g*4+0] += a0 * wv.x; acc[0][g*4+1] += a0 * wv.y;
                    acc[0][g*4+2] += a0 * wv.z; acc[0][g*4+3] += a0 * wv.w;
                    acc[1][g*4+0] += a1 * wv.x; acc[1][g*4+1] += a1 * wv.y;
                    acc[1][g*4+2] += a1 * wv.z; acc[1][g*4+3] += a1 * wv.w;
                    acc[2][g*4+0] += a2 * wv.x; acc[2][g*4+1] += a2 * wv.y;
                    acc[2][g*4+2] += a2 * wv.z; acc[2][g*4+3] += a2 * wv.w;
                    acc[3][g*4+0] += a3 * wv.x; acc[3][g*4+1] += a3 * wv.y;
                    acc[3][g*4+2] += a3 * wv.z; acc[3][g*4+3] += a3 * wv.w;
                }
                ap += XS_PITCH;
                wp += NC;
            }
        }
    }

    // ================= fused LSTM epilogue =================
    const int bcol = nt * 4;
    const float4 bv0 = *(const float4*)(bias +   0 + bcol);
    const float4 bv1 = *(const float4*)(bias +  64 + bcol);
    const float4 bv2 = *(const float4*)(bias + 128 + bcol);
    const float4 bv3 = *(const float4*)(bias + 192 + bcol);

    float* hout = last ? outbuf : g_h[hsel ^ 1];
    const size_t bbase = (size_t)b * H_ * W_ * F_;
    const int gy = ty0 + sy;

    #pragma unroll
    for (int m = 0; m < 4; ++m) {
        const int gx = tx0 + sxb + m;
        const size_t idx = bbase + ((size_t)gy * W_ + gx) * F_ + bcol;
        float4 cold = make_float4(0.f, 0.f, 0.f, 0.f);
        if (!FIRST) cold = *(const float4*)(g_c + idx);
        float4 cn, hn;
        {
            float ig = hsig(acc[m][0]  + bv0.x);
            float fg = hsig(acc[m][4]  + bv1.x);
            float zc =      acc[m][8]  + bv2.x;
            float og = hsig(acc[m][12] + bv3.x);
            float cv = fg * cold.x + ig * fmaxf(zc, 0.f);
            cn.x = cv; hn.x = og * fmaxf(cv, 0.f);
        }
        {
            float ig = hsig(acc[m][1]  + bv0.y);
            float fg = hsig(acc[m][5]  + bv1.y);
            float zc =      acc[m][9]  + bv2.y;
            float og = hsig(acc[m][13] + bv3.y);
            float cv = fg * cold.y + ig * fmaxf(zc, 0.f);
            cn.y = cv; hn.y = og * fmaxf(cv, 0.f);
        }
        {
            float ig = hsig(acc[m][2]  + bv0.z);
            float fg = hsig(acc[m][6]  + bv1.z);
            float zc =      acc[m][10] + bv2.z;
            float og = hsig(acc[m][14] + bv3.z);
            float cv = fg * cold.z + ig * fmaxf(zc, 0.f);
            cn.z = cv; hn.z = og * fmaxf(cv, 0.f);
        }
        {
            float ig = hsig(acc[m][3]  + bv0.w);
            float fg = hsig(acc[m][7]  + bv1.w);
            float zc =      acc[m][11] + bv2.w;
            float og = hsig(acc[m][15] + bv3.w);
            float cv = fg * cold.w + ig * fmaxf(zc, 0.f);
            cn.w = cv; hn.w = og * fmaxf(cv, 0.f);
        }
        *(float4*)(g_c + idx) = cn;
        *(float4*)(hout + idx) = hn;
    }
}

extern "C" void kernel_launch(void* const* d_in, const int* in_sizes, int n_in,
                              void* d_out, int out_size)
{
    // Map inputs by element count (robust to ordering): x, W, U, b
    const float* x = nullptr; const float* Wt = nullptr;
    const float* Ut = nullptr; const float* bias = nullptr;
    for (int i = 0; i < n_in; ++i) {
        switch (in_sizes[i]) {
            case B_*T_*H_*W_*CIN: x    = (const float*)d_in[i]; break;  // 16777216
            case 3*3*CIN*NC:      Wt   = (const float*)d_in[i]; break;  // 73728
            case 3*3*F_*NC:       Ut   = (const float*)d_in[i]; break;  // 147456
            case NC:              bias = (const float*)d_in[i]; break;  // 256
        }
    }
    if (!x || !Wt || !Ut || !bias) {
        // Fallback to declared order
        x = (const float*)d_in[0]; Wt = (const float*)d_in[1];
        Ut = (const float*)d_in[2]; bias = (const float*)d_in[3];
    }
    float* out = (float*)d_out;

    const int smem_bytes = (F_ * NC + CIN * XS_PITCH + F_ * XS_PITCH) * (int)sizeof(float);
    cudaFuncSetAttribute(step_kernel<true>,
                         cudaFuncAttributeMaxDynamicSharedMemorySize, smem_bytes);
    cudaFuncSetAttribute(step_kernel<false>,
                         cudaFuncAttributeMaxDynamicSharedMemorySize, smem_bytes);

    dim3 grid(64, B_);
    dim3 block(256);

    // t = 0: h = c = 0 (no recurrent conv, no state read); writes g_h[1]
    step_kernel<true><<<grid, block, smem_bytes>>>(x, Wt, Ut, bias, 0, 0, out, 0);
    // t = 1..15: read g_h[t&1], write g_h[(t&1)^1]; last writes d_out
    for (int t = 1; t < T_; ++t) {
        int last = (t == T_ - 1);
        step_kernel<false><<<grid, block, smem_bytes>>>(x, Wt, Ut, bias, t,
                                                        t & 1, out, last);
    }
}

// round 3
// speedup vs baseline: 1.1337x; 1.1337x over previous
#include <cuda_runtime.h>

#define B_   8
#define T_   16
#define H_   64
#define W_   64
#define CIN  32
#define F_   64
#define NC   256          // 4*F (gates i,f,c,o stacked)
#define XS_PITCH 101      // padded per-channel stride for halo tiles

// Persistent recurrent state (no allocation allowed). FIRST-step template
// ignores these on read, so no zero-init is needed -> deterministic replays.
__device__ float g_h[2][B_ * H_ * W_ * F_];
__device__ float g_c[B_ * H_ * W_ * F_];

__device__ __forceinline__ float hsig(float x) {
    // jax.nn.hard_sigmoid = relu6(x+3)/6 = clip((x+3)/6, 0, 1)
    return __saturatef((x + 3.0f) * 0.16666667f);
}

// ---- packed fp32x2 helpers (FFMA2: 2 fp32 FMAs per issue slot) ----
__device__ __forceinline__ unsigned long long pack2(float a, float b) {
    unsigned long long r;
    asm("mov.b64 %0, {%1, %2};" : "=l"(r) : "f"(a), "f"(b));
    return r;
}
__device__ __forceinline__ unsigned long long packdup(float a) {
    unsigned long long r;
    asm("mov.b64 %0, {%1, %1};" : "=l"(r) : "f"(a));
    return r;
}
__device__ __forceinline__ void ffma2(unsigned long long& d,
                                      unsigned long long a,
                                      unsigned long long b) {
    asm("fma.rn.f32x2 %0, %1, %2, %0;" : "+l"(d) : "l"(a), "l"(b));
}
__device__ __forceinline__ void unpack2(unsigned long long v, float& a, float& b) {
    asm("mov.b64 {%0, %1}, %2;" : "=f"(a), "=f"(b) : "l"(v));
}

// One ConvLSTM timestep. Block = (batch, 8x8 spatial tile), 256 threads.
// Warp mapping (crossbar-friendly):
//   warp = (wpx: 2 pixel halves) x (wcol: 4 col quarters)
//   lane = (pl: 8 pixel-groups of 4 consecutive x) x (nl: 4 col subgroups)
//   thread tile: 4 pixels x 16 cols (4 per gate) -> epilogue thread-local.
//   Weight LDS.128 address depends only on nl -> 64B/warp -> 1 wavefront.
//   Activation scalar LDS depends only on pl -> 8 banks -> 1 wavefront.
template<bool FIRST>
__global__ __launch_bounds__(256, 2)
void step_kernel(const float* __restrict__ x,
                 const float* __restrict__ Wt,   // (3,3,32,256)
                 const float* __restrict__ Ut,   // (3,3,64,256)
                 const float* __restrict__ bias, // (256)
                 int t, int hsel,
                 float* __restrict__ outbuf, int last)
{
    extern __shared__ float smem[];
    float* ws = smem;                         // weight slice: up to 64*256
    float* xs = smem + F_ * NC;               // x halo: [32][101]
    float* hs = xs + CIN * XS_PITCH;          // h halo: [64][101]

    const int tid  = threadIdx.x;
    const int b    = blockIdx.y;
    const int ty0  = (blockIdx.x >> 3) << 3;
    const int tx0  = (blockIdx.x & 7) << 3;

    const int warp = tid >> 5;
    const int lane = tid & 31;
    const int pl   = lane >> 2;          // 0..7  pixel group
    const int nl   = lane & 3;           // 0..3  col subgroup
    const int sy   = (warp & 1) * 4 + (pl >> 1);   // tile row 0..7
    const int sxb  = (pl & 1) << 2;                // tile col base {0,4}
    const int bcol = (warp >> 1) * 16 + nl * 4;    // 0..60, per-gate col base

    // ---- stage x halo tile: xs[c][p], p = py*10 + px ----
    {
        const float* xb = x + (size_t)(b * T_ + t) * H_ * W_ * CIN;
        for (int j = tid; j < 100 * (CIN / 4); j += 256) {
            int p  = j >> 3;
            int v  = j & 7;
            int py = p / 10, px = p - 10 * py;
            int gy = ty0 + py - 1, gx = tx0 + px - 1;
            float4 val = make_float4(0.f, 0.f, 0.f, 0.f);
            if ((unsigned)gy < H_ && (unsigned)gx < W_)
                val = *(const float4*)(xb + ((size_t)gy * W_ + gx) * CIN + v * 4);
            int c0 = v * 4;
            xs[(c0 + 0) * XS_PITCH + p] = val.x;
            xs[(c0 + 1) * XS_PITCH + p] = val.y;
            xs[(c0 + 2) * XS_PITCH + p] = val.z;
            xs[(c0 + 3) * XS_PITCH + p] = val.w;
        }
    }
    // ---- stage h halo tile ----
    if (!FIRST) {
        const float* hb = g_h[hsel] + (size_t)b * H_ * W_ * F_;
        for (int j = tid; j < 100 * (F_ / 4); j += 256) {
            int p  = j >> 4;
            int v  = j & 15;
            int py = p / 10, px = p - 10 * py;
            int gy = ty0 + py - 1, gx = tx0 + px - 1;
            float4 val = make_float4(0.f, 0.f, 0.f, 0.f);
            if ((unsigned)gy < H_ && (unsigned)gx < W_)
                val = *(const float4*)(hb + ((size_t)gy * W_ + gx) * F_ + v * 4);
            int c0 = v * 4;
            hs[(c0 + 0) * XS_PITCH + p] = val.x;
            hs[(c0 + 1) * XS_PITCH + p] = val.y;
            hs[(c0 + 2) * XS_PITCH + p] = val.z;
            hs[(c0 + 3) * XS_PITCH + p] = val.w;
        }
    }

    // packed accumulators: pacc[m][g*2 + pr] holds cols (bcol+2pr, bcol+2pr+1) of gate g
    unsigned long long pacc[4][8];
    #pragma unroll
    for (int m = 0; m < 4; ++m)
        #pragma unroll
        for (int r = 0; r < 8; ++r) pacc[m][r] = 0ull;

    // ================= input conv: z += conv(x_t, W) =================
    for (int k9 = 0; k9 < 9; ++k9) {
        __syncthreads();   // tiles staged (k9==0) / previous ws reads done
        {
            const float4* src = (const float4*)(Wt + (size_t)k9 * CIN * NC);
            float4* dst = (float4*)ws;
            #pragma unroll
            for (int j = 0; j < (CIN * NC / 4) / 256; ++j)
                dst[tid + j * 256] = src[tid + j * 256];
        }
        __syncthreads();
        const int ky = k9 / 3, kx = k9 - 3 * (k9 / 3);
        const float* ap = xs + (sy + ky) * 10 + sxb + kx;
        const float* wp = ws + bcol;
        #pragma unroll 4
        for (int c = 0; c < CIN; ++c) {
            unsigned long long pa0 = packdup(ap[0]);
            unsigned long long pa1 = packdup(ap[1]);
            unsigned long long pa2 = packdup(ap[2]);
            unsigned long long pa3 = packdup(ap[3]);
            #pragma unroll
            for (int g = 0; g < 4; ++g) {
                float4 wv = *(const float4*)(wp + g * 64);
                unsigned long long w01 = pack2(wv.x, wv.y);
                unsigned long long w23 = pack2(wv.z, wv.w);
                ffma2(pacc[0][g*2+0], pa0, w01); ffma2(pacc[0][g*2+1], pa0, w23);
                ffma2(pacc[1][g*2+0], pa1, w01); ffma2(pacc[1][g*2+1], pa1, w23);
                ffma2(pacc[2][g*2+0], pa2, w01); ffma2(pacc[2][g*2+1], pa2, w23);
                ffma2(pacc[3][g*2+0], pa3, w01); ffma2(pacc[3][g*2+1], pa3, w23);
            }
            ap += XS_PITCH;
            wp += NC;
        }
    }

    // ================= recurrent conv: z += conv(h, U) =================
    if (!FIRST) {
        for (int k9 = 0; k9 < 9; ++k9) {
            __syncthreads();
            {
                const float4* src = (const float4*)(Ut + (size_t)k9 * F_ * NC);
                float4* dst = (float4*)ws;
                #pragma unroll
                for (int j = 0; j < (F_ * NC / 4) / 256; ++j)
                    dst[tid + j * 256] = src[tid + j * 256];
            }
            __syncthreads();
            const int ky = k9 / 3, kx = k9 - 3 * (k9 / 3);
            const float* ap = hs + (sy + ky) * 10 + sxb + kx;
            const float* wp = ws + bcol;
            #pragma unroll 4
            for (int c = 0; c < F_; ++c) {
                unsigned long long pa0 = packdup(ap[0]);
                unsigned long long pa1 = packdup(ap[1]);
                unsigned long long pa2 = packdup(ap[2]);
                unsigned long long pa3 = packdup(ap[3]);
                #pragma unroll
                for (int g = 0; g < 4; ++g) {
                    float4 wv = *(const float4*)(wp + g * 64);
                    unsigned long long w01 = pack2(wv.x, wv.y);
                    unsigned long long w23 = pack2(wv.z, wv.w);
                    ffma2(pacc[0][g*2+0], pa0, w01); ffma2(pacc[0][g*2+1], pa0, w23);
                    ffma2(pacc[1][g*2+0], pa1, w01); ffma2(pacc[1][g*2+1], pa1, w23);
                    ffma2(pacc[2][g*2+0], pa2, w01); ffma2(pacc[2][g*2+1], pa2, w23);
                    ffma2(pacc[3][g*2+0], pa3, w01); ffma2(pacc[3][g*2+1], pa3, w23);
                }
                ap += XS_PITCH;
                wp += NC;
            }
        }
    }

    // ================= fused LSTM epilogue =================
    const float4 bv0 = *(const float4*)(bias +   0 + bcol);
    const float4 bv1 = *(const float4*)(bias +  64 + bcol);
    const float4 bv2 = *(const float4*)(bias + 128 + bcol);
    const float4 bv3 = *(const float4*)(bias + 192 + bcol);

    float* hout = last ? outbuf : g_h[hsel ^ 1];
    const size_t bbase = (size_t)b * H_ * W_ * F_;
    const int gy = ty0 + sy;

    #pragma unroll
    for (int m = 0; m < 4; ++m) {
        const int gx = tx0 + sxb + m;
        const size_t idx = bbase + ((size_t)gy * W_ + gx) * F_ + bcol;
        float4 cold = make_float4(0.f, 0.f, 0.f, 0.f);
        if (!FIRST) cold = *(const float4*)(g_c + idx);

        float zi[4], zf[4], zc[4], zo[4];
        unpack2(pacc[m][0], zi[0], zi[1]); unpack2(pacc[m][1], zi[2], zi[3]);
        unpack2(pacc[m][2], zf[0], zf[1]); unpack2(pacc[m][3], zf[2], zf[3]);
        unpack2(pacc[m][4], zc[0], zc[1]); unpack2(pacc[m][5], zc[2], zc[3]);
        unpack2(pacc[m][6], zo[0], zo[1]); unpack2(pacc[m][7], zo[2], zo[3]);

        float4 cn, hn;
        {
            float ig = hsig(zi[0] + bv0.x);
            float fg = hsig(zf[0] + bv1.x);
            float zz =      zc[0] + bv2.x;
            float og = hsig(zo[0] + bv3.x);
            float cv = fg * cold.x + ig * fmaxf(zz, 0.f);
            cn.x = cv; hn.x = og * fmaxf(cv, 0.f);
        }
        {
            float ig = hsig(zi[1] + bv0.y);
            float fg = hsig(zf[1] + bv1.y);
            float zz =      zc[1] + bv2.y;
            float og = hsig(zo[1] + bv3.y);
            float cv = fg * cold.y + ig * fmaxf(zz, 0.f);
            cn.y = cv; hn.y = og * fmaxf(cv, 0.f);
        }
        {
            float ig = hsig(zi[2] + bv0.z);
            float fg = hsig(zf[2] + bv1.z);
            float zz =      zc[2] + bv2.z;
            float og = hsig(zo[2] + bv3.z);
            float cv = fg * cold.z + ig * fmaxf(zz, 0.f);
            cn.z = cv; hn.z = og * fmaxf(cv, 0.f);
        }
        {
            float ig = hsig(zi[3] + bv0.w);
            float fg = hsig(zf[3] + bv1.w);
            float zz =      zc[3] + bv2.w;
            float og = hsig(zo[3] + bv3.w);
            float cv = fg * cold.w + ig * fmaxf(zz, 0.f);
            cn.w = cv; hn.w = og * fmaxf(cv, 0.f);
        }
        if (!last) *(float4*)(g_c + idx) = cn;
        *(float4*)(hout + idx) = hn;
    }
}

extern "C" void kernel_launch(void* const* d_in, const int* in_sizes, int n_in,
                              void* d_out, int out_size)
{
    // Map inputs by element count (robust to ordering): x, W, U, b
    const float* x = nullptr; const float* Wt = nullptr;
    const float* Ut = nullptr; const float* bias = nullptr;
    for (int i = 0; i < n_in; ++i) {
        switch (in_sizes[i]) {
            case B_*T_*H_*W_*CIN: x    = (const float*)d_in[i]; break;  // 16777216
            case 3*3*CIN*NC:      Wt   = (const float*)d_in[i]; break;  // 73728
            case 3*3*F_*NC:       Ut   = (const float*)d_in[i]; break;  // 147456
            case NC:              bias = (const float*)d_in[i]; break;  // 256
        }
    }
    if (!x || !Wt || !Ut || !bias) {
        x = (const float*)d_in[0]; Wt = (const float*)d_in[1];
        Ut = (const float*)d_in[2]; bias = (const float*)d_in[3];
    }
    float* out = (float*)d_out;

    const int smem_bytes = (F_ * NC + CIN * XS_PITCH + F_ * XS_PITCH) * (int)sizeof(float);
    cudaFuncSetAttribute(step_kernel<true>,
                         cudaFuncAttributeMaxDynamicSharedMemorySize, smem_bytes);
    cudaFuncSetAttribute(step_kernel<false>,
                         cudaFuncAttributeMaxDynamicSharedMemorySize, smem_bytes);

    dim3 grid(64, B_);
    dim3 block(256);

    // t = 0: h = c = 0 (no recurrent conv, no state read); writes g_h[1]
    step_kernel<true><<<grid, block, smem_bytes>>>(x, Wt, Ut, bias, 0, 0, out, 0);
    // t = 1..15: read g_h[t&1], write g_h[(t&1)^1]; last writes d_out
    for (int t = 1; t < T_; ++t) {
        int last = (t == T_ - 1);
        step_kernel<false><<<grid, block, smem_bytes>>>(x, Wt, Ut, bias, t,
                                                        t & 1, out, last);
    }
}

// round 5
// speedup vs baseline: 4.4311x; 3.9087x over previous
#include <cuda_runtime.h>
#include <cuda_fp16.h>
#include <cstdint>

#define B_   8
#define T_   16
#define H_   64
#define W_   64
#define CIN  32
#define F_   64
#define NC   256          // 4*F gates [i,f,c,o]
#define NSLICE 27         // 9 x-conv (K=32) + 18 h-conv (K=32 halves)

// Persistent state. h in fp16 (feeds fp16 MMA), c in fp32.
__device__ __half g_hh[2][B_ * H_ * W_ * F_];
__device__ float  g_c[B_ * H_ * W_ * F_];
// Pre-transposed, gate-permuted fp16 weights: [slice][nSm][k]
// nSm = warp_n*64 + g*16 + fi  ->  source col = g*64 + (warp_n*16 + fi)
__device__ __half g_wtr[NSLICE][256][32];

__device__ __forceinline__ float hsig(float x) {
    return __saturatef((x + 3.0f) * 0.16666667f);  // hard_sigmoid
}
__device__ __forceinline__ uint32_t smem_u32(const void* p) {
    uint32_t a;
    asm("{ .reg .u64 t; cvta.to.shared.u64 t, %1; cvt.u32.u64 %0, t; }"
        : "=r"(a) : "l"(p));
    return a;
}

#define LDSM4(r0, r1, r2, r3, addr) \
    asm volatile("ldmatrix.sync.aligned.m8n8.x4.shared.b16 {%0,%1,%2,%3}, [%4];" \
        : "=r"(r0), "=r"(r1), "=r"(r2), "=r"(r3) : "r"(addr))

#define MMA16816(d, a0, a1, a2, a3, b0, b1) \
    asm volatile("mma.sync.aligned.m16n8k16.row.col.f32.f16.f16.f32 " \
        "{%0,%1,%2,%3}, {%4,%5,%6,%7}, {%8,%9}, {%0,%1,%2,%3};" \
        : "+f"((d)[0]), "+f"((d)[1]), "+f"((d)[2]), "+f"((d)[3]) \
        : "r"(a0), "r"(a1), "r"(a2), "r"(a3), "r"(b0), "r"(b1))

// ---- one-time weight transpose/permute/convert (captured in graph; cheap) ----
__global__ void prep_weights(const float* __restrict__ Wt,
                             const float* __restrict__ Ut)
{
    const int s = blockIdx.x;       // 0..26
    const int n = threadIdx.x;      // 0..255  (nSm)
    const int g  = (n >> 4) & 3;
    const int f  = (n >> 6) * 16 + (n & 15);
    const int j  = g * 64 + f;      // source output-column
    const float* src;
    if (s < 9) {
        src = Wt + (size_t)s * CIN * NC;
    } else {
        int u = s - 9;
        src = Ut + (size_t)(u >> 1) * F_ * NC + (size_t)((u & 1) * 32) * NC;
    }
    #pragma unroll 8
    for (int k = 0; k < 32; ++k)
        g_wtr[s][n][k] = __float2half_rn(src[(size_t)k * NC + j]);
}

// One ConvLSTM timestep via mma.sync (HMMA) implicit GEMM.
// CTA: 8x8 pixel tile (M=64) x N=256. 8 warps: warp_m (2) x warp_n (4).
// Warp tile 32 x 64 (64 cols = 16 f-values x 4 gates, permuted).
template<bool FIRST>
__global__ __launch_bounds__(256, 2)
void step_mma(const float* __restrict__ x, const float* __restrict__ bias,
              int t, int hsel, float* __restrict__ out, int last)
{
    __shared__ __half sA[64][40];     // 80B pitch (conflict-free ldmatrix)
    __shared__ __half sB[256][40];

    const int tid  = threadIdx.x;
    const int lane = tid & 31;
    const int w    = tid >> 5;
    const int warp_m = w & 1;
    const int warp_n = w >> 1;
    const int b  = blockIdx.z;
    const int y0 = blockIdx.y * 8;
    const int x0 = blockIdx.x * 8;

    const float*  xframe = x + (size_t)(b * T_ + t) * H_ * W_ * CIN;
    const __half* hframe = g_hh[hsel] + (size_t)b * H_ * W_ * F_;

    const uint32_t saA = smem_u32(&sA[0][0]);
    const uint32_t saB = smem_u32(&sB[0][0]);

    float d[2][8][4];
    #pragma unroll
    for (int mt = 0; mt < 2; ++mt)
        #pragma unroll
        for (int nt = 0; nt < 8; ++nt)
            #pragma unroll
            for (int c = 0; c < 4; ++c) d[mt][nt][c] = 0.f;

    // staging coords
    const int arow = tid >> 2, q = tid & 3;            // A: row, 16B quarter
    const int apy = arow >> 3, apx = arow & 7;

    const int NS = FIRST ? 9 : NSLICE;
    for (int s = 0; s < NS; ++s) {
        int k9, c0;
        if (s < 9) { k9 = s; c0 = 0; }
        else       { int u = s - 9; k9 = u >> 1; c0 = (u & 1) * 32; }
        const int ky = k9 / 3, kx = k9 - 3 * (k9 / 3);

        // ---- stage A: 64 rows x 32 fp16 ----
        {
            const int gy = y0 + apy + ky - 1;
            const int gx = x0 + apx + kx - 1;
            const bool ok = (unsigned)gy < H_ && (unsigned)gx < W_;
            uint4 val = make_uint4(0u, 0u, 0u, 0u);
            if (s < 9) {
                if (ok) {
                    const float4* sp = (const float4*)
                        (xframe + ((size_t)gy * W_ + gx) * CIN + q * 8);
                    float4 v0 = sp[0], v1 = sp[1];
                    __half2 hh[4];
                    hh[0] = __floats2half2_rn(v0.x, v0.y);
                    hh[1] = __floats2half2_rn(v0.z, v0.w);
                    hh[2] = __floats2half2_rn(v1.x, v1.y);
                    hh[3] = __floats2half2_rn(v1.z, v1.w);
                    val = *(const uint4*)hh;
                }
            } else {
                if (ok)
                    val = *(const uint4*)
                        (hframe + ((size_t)gy * W_ + gx) * F_ + c0 + q * 8);
            }
            *(uint4*)&sA[arow][q * 8] = val;
        }
        // ---- stage B: 256 rows x 32 fp16 (pre-permuted) ----
        {
            const uint4* wr = (const uint4*)g_wtr[s][tid];
            uint4 b0 = wr[0], b1 = wr[1], b2 = wr[2], b3 = wr[3];
            *(uint4*)&sB[tid][0]  = b0;
            *(uint4*)&sB[tid][8]  = b1;
            *(uint4*)&sB[tid][16] = b2;
            *(uint4*)&sB[tid][24] = b3;
        }
        __syncthreads();

        // ---- 32 mma per warp ----
        #pragma unroll
        for (int kk = 0; kk < 2; ++kk) {
            uint32_t a[2][4];
            #pragma unroll
            for (int mt = 0; mt < 2; ++mt) {
                uint32_t ad = saA
                    + (uint32_t)(warp_m * 32 + mt * 16 + (lane & 15)) * 80u
                    + (uint32_t)(kk * 32 + ((lane >> 4) << 4));
                LDSM4(a[mt][0], a[mt][1], a[mt][2], a[mt][3], ad);
            }
            #pragma unroll
            for (int p = 0; p < 4; ++p) {
                uint32_t n = (uint32_t)(warp_n * 64 + p * 16
                                        + ((lane >> 4) << 3) + (lane & 7));
                uint32_t bd = saB + n * 80u
                    + (uint32_t)(kk * 32 + (((lane >> 3) & 1) << 4));
                uint32_t b0, b1, b2, b3;
                LDSM4(b0, b1, b2, b3, bd);
                MMA16816(d[0][2 * p + 0], a[0][0], a[0][1], a[0][2], a[0][3], b0, b1);
                MMA16816(d[0][2 * p + 1], a[0][0], a[0][1], a[0][2], a[0][3], b2, b3);
                MMA16816(d[1][2 * p + 0], a[1][0], a[1][1], a[1][2], a[1][3], b0, b1);
                MMA16816(d[1][2 * p + 1], a[1][0], a[1][1], a[1][2], a[1][3], b2, b3);
            }
        }
        __syncthreads();
    }

    // ================= fused LSTM epilogue =================
    // D frag: (d0,d1)=row lane>>2, cols 2(lane&3)+{0,1}; (d2,d3)=row+8.
    // Ntile nt = 2g + t1  ->  gate g, f = warp_n*16 + t1*8 + 2(lane&3)+{0,1}
    __half* hhout = g_hh[hsel ^ 1];
    const int fq = 2 * (lane & 3);

    #pragma unroll
    for (int mt = 0; mt < 2; ++mt) {
        #pragma unroll
        for (int rh = 0; rh < 2; ++rh) {
            const int m  = warp_m * 32 + mt * 16 + rh * 8 + (lane >> 2);
            const int py = m >> 3, px = m & 7;
            const size_t pix =
                (((size_t)b * H_ + (y0 + py)) * W_ + (x0 + px)) * F_;
            #pragma unroll
            for (int t1 = 0; t1 < 2; ++t1) {
                const int f0 = warp_n * 16 + t1 * 8 + fq;
                float zi0 = d[mt][0 + t1][rh * 2 + 0], zi1 = d[mt][0 + t1][rh * 2 + 1];
                float zf0 = d[mt][2 + t1][rh * 2 + 0], zf1 = d[mt][2 + t1][rh * 2 + 1];
                float zc0 = d[mt][4 + t1][rh * 2 + 0], zc1 = d[mt][4 + t1][rh * 2 + 1];
                float zo0 = d[mt][6 + t1][rh * 2 + 0], zo1 = d[mt][6 + t1][rh * 2 + 1];

                float2 co = make_float2(0.f, 0.f);
                if (!FIRST) co = *(const float2*)&g_c[pix + f0];

                float ig0 = hsig(zi0 + bias[f0]);
                float fg0 = hsig(zf0 + bias[64 + f0]);
                float zz0 =      zc0 + bias[128 + f0];
                float og0 = hsig(zo0 + bias[192 + f0]);
                float cn0 = fg0 * co.x + ig0 * fmaxf(zz0, 0.f);
                float hn0 = og0 * fmaxf(cn0, 0.f);

                float ig1 = hsig(zi1 + bias[f0 + 1]);
                float fg1 = hsig(zf1 + bias[65 + f0]);
                float zz1 =      zc1 + bias[129 + f0];
                float og1 = hsig(zo1 + bias[193 + f0]);
                float cn1 = fg1 * co.y + ig1 * fmaxf(zz1, 0.f);
                float hn1 = og1 * fmaxf(cn1, 0.f);

                if (!last) {
                    *(float2*)&g_c[pix + f0] = make_float2(cn0, cn1);
                    *(__half2*)&hhout[pix + f0] = __floats2half2_rn(hn0, hn1);
                } else {
                    *(float2*)&out[pix + f0] = make_float2(hn0, hn1);
                }
            }
        }
    }
}

extern "C" void kernel_launch(void* const* d_in, const int* in_sizes, int n_in,
                              void* d_out, int out_size)
{
    const float* x = nullptr; const float* Wt = nullptr;
    const float* Ut = nullptr; const float* bias = nullptr;
    for (int i = 0; i < n_in; ++i) {
        switch (in_sizes[i]) {
            case B_*T_*H_*W_*CIN: x    = (const float*)d_in[i]; break;
            case 3*3*CIN*NC:      Wt   = (const float*)d_in[i]; break;
            case 3*3*F_*NC:       Ut   = (const float*)d_in[i]; break;
            case NC:              bias = (const float*)d_in[i]; break;
        }
    }
    if (!x || !Wt || !Ut || !bias) {
        x = (const float*)d_in[0]; Wt = (const float*)d_in[1];
        Ut = (const float*)d_in[2]; bias = (const float*)d_in[3];
    }
    float* out = (float*)d_out;

    prep_weights<<<NSLICE, 256>>>(Wt, Ut);

    dim3 grid(W_ / 8, H_ / 8, B_);    // (8, 8, 8) = 512 CTAs
    dim3 block(256);

    // t = 0: h = c = 0; writes g_hh[1], g_c
    step_mma<true><<<grid, block>>>(x, bias, 0, 0, out, 0);
    for (int t = 1; t < T_; ++t) {
        int last = (t == T_ - 1);
        step_mma<false><<<grid, block>>>(x, bias, t, t & 1, out, last);
    }
}